// round 1
// baseline (speedup 1.0000x reference)
#include <cuda_runtime.h>
#include <cstddef>

// Problem constants (fixed by dataset)
#define N_NODES 50000
#define N_EDGES 800000
#define IN_C    256
#define H2_C    256   // 2*H
#define H_C     128
#define OUT_C   64

// ------------------------- scratch (device globals; no allocs) -------------
__device__ float g_H1 [(size_t)N_NODES * H2_C];   // seq @ W1
__device__ float g_X1 [(size_t)N_NODES * H2_C];   // prelu(agg1 + b1)
__device__ float g_H2 [(size_t)N_NODES * H_C];    // X1 @ W2
__device__ float g_T  [(size_t)N_NODES * OUT_C];  // seq @ U
__device__ float g_M34[512 * OUT_C];              // Wfc3 @ Wfc4
__device__ float g_U  [256 * OUT_C];              // Wfc2 @ M34[:256]
__device__ float g_V  [128 * OUT_C];              // Wfc1 @ M34[256:]
__device__ int   g_deg[N_NODES];                  // degree / fill cursor
__device__ int   g_rowptr[N_NODES + 1];
__device__ int   g_part[256];                     // scan partials
__device__ int   g_csr_src[N_EDGES];
__device__ float g_csr_w [N_EDGES];

static const int NB_SCAN = (N_NODES + 255) / 256;   // 196 (<256)

// ------------------------- small utility kernels ---------------------------
__global__ void k_zero_int(int* p, int n) {
    int i = blockIdx.x * blockDim.x + threadIdx.x;
    if (i < n) p[i] = 0;
}

__global__ void k_count(const int* __restrict__ dst) {
    int e = blockIdx.x * blockDim.x + threadIdx.x;
    if (e < N_EDGES) atomicAdd(&g_deg[dst[e]], 1);
}

// block sums of g_deg in 256-chunks
__global__ void k_blocksum() {
    __shared__ int s[256];
    int t = threadIdx.x;
    int i = blockIdx.x * 256 + t;
    s[t] = (i < N_NODES) ? g_deg[i] : 0;
    __syncthreads();
    for (int off = 128; off > 0; off >>= 1) {
        if (t < off) s[t] += s[t + off];
        __syncthreads();
    }
    if (t == 0) g_part[blockIdx.x] = s[0];
}

// exclusive scan of g_part (single block, 256 threads)
__global__ void k_scanpart() {
    __shared__ int s[256];
    int t = threadIdx.x;
    s[t] = (t < NB_SCAN) ? g_part[t] : 0;
    __syncthreads();
    for (int off = 1; off < 256; off <<= 1) {
        int add = (t >= off) ? s[t - off] : 0;
        __syncthreads();
        s[t] += add;
        __syncthreads();
    }
    // inclusive -> exclusive
    g_part[t] = (t == 0) ? 0 : s[t - 1];
}

// per-chunk inclusive scan + offset -> rowptr
__global__ void k_scanfinal() {
    __shared__ int s[256];
    int t = threadIdx.x;
    int i = blockIdx.x * 256 + t;
    int v = (i < N_NODES) ? g_deg[i] : 0;
    s[t] = v;
    __syncthreads();
    for (int off = 1; off < 256; off <<= 1) {
        int add = (t >= off) ? s[t - off] : 0;
        __syncthreads();
        s[t] += add;
        __syncthreads();
    }
    if (i < N_NODES) g_rowptr[i + 1] = s[t] + g_part[blockIdx.x];
    if (i == 0)      g_rowptr[0] = 0;
}

__global__ void k_fill(const int* __restrict__ src, const int* __restrict__ dst,
                       const float* __restrict__ w) {
    int e = blockIdx.x * blockDim.x + threadIdx.x;
    if (e >= N_EDGES) return;
    int d = dst[e];
    int pos = g_rowptr[d] + atomicAdd(&g_deg[d], 1);  // g_deg re-zeroed as cursor
    g_csr_src[pos] = src[e];
    g_csr_w [pos] = w[e];
}

// ---------------- CSR aggregation: one warp per node, fused bias+PReLU -----
template <int C>
__global__ void k_agg(const float* __restrict__ h,
                      const float* __restrict__ bias,
                      const float* __restrict__ act,
                      float* __restrict__ out) {
    int gw   = (blockIdx.x * blockDim.x + threadIdx.x) >> 5;
    int lane = threadIdx.x & 31;
    if (gw >= N_NODES) return;
    constexpr int V4 = C / 128;       // float4 chunks per lane
    float4 acc[V4];
#pragma unroll
    for (int i = 0; i < V4; i++) acc[i] = make_float4(0.f, 0.f, 0.f, 0.f);

    int beg = g_rowptr[gw], end = g_rowptr[gw + 1];
    for (int j = beg; j < end; j++) {
        int   s = g_csr_src[j];
        float w = g_csr_w[j];
        const float4* row = (const float4*)(h + (size_t)s * C);
#pragma unroll
        for (int i = 0; i < V4; i++) {
            float4 v = row[lane + 32 * i];
            acc[i].x += w * v.x;
            acc[i].y += w * v.y;
            acc[i].z += w * v.z;
            acc[i].w += w * v.w;
        }
    }
    float a = act[0];
    const float4* b4 = (const float4*)bias;
    float4* o4 = (float4*)(out + (size_t)gw * C);
#pragma unroll
    for (int i = 0; i < V4; i++) {
        float4 bv = b4[lane + 32 * i];
        float4 r;
        r.x = acc[i].x + bv.x; r.x = r.x >= 0.f ? r.x : a * r.x;
        r.y = acc[i].y + bv.y; r.y = r.y >= 0.f ? r.y : a * r.y;
        r.z = acc[i].z + bv.z; r.z = r.z >= 0.f ? r.z : a * r.z;
        r.w = acc[i].w + bv.w; r.w = r.w >= 0.f ? r.w : a * r.w;
        o4[lane + 32 * i] = r;
    }
}

// ---------------- generic fp32 SGEMM: C = A[MxK] @ B[KxN] (+Cadd) (+prelu) --
// BM=128 BN=64 BK=16, 256 threads, 8x4 per-thread micro-tile.
// Requires: K % 16 == 0, N % 64 == 0 (true for all calls here). M arbitrary.
__global__ __launch_bounds__(256)
void k_gemm(const float* __restrict__ A, const float* __restrict__ B,
            const float* __restrict__ Cadd, const float* __restrict__ act,
            float* __restrict__ Cout, int M, int K, int Nn) {
    __shared__ float As[16][128];
    __shared__ float Bs[16][64];
    const int tid = threadIdx.x;
    const int tx = tid & 15;      // n-dir (x4 cols)
    const int ty = tid >> 4;      // m-dir (x8 rows)
    const int bm = blockIdx.y * 128;
    const int bn = blockIdx.x * 64;

    const int a_r = tid >> 2;            // 0..63 (+64 for second half)
    const int a_k = (tid & 3) << 2;      // k offset within BK
    const int b_k = tid >> 4;            // 0..15
    const int b_n = (tid & 15) << 2;     // 0..60

    float acc[8][4];
#pragma unroll
    for (int i = 0; i < 8; i++)
#pragma unroll
        for (int j = 0; j < 4; j++) acc[i][j] = 0.f;

    for (int k0 = 0; k0 < K; k0 += 16) {
#pragma unroll
        for (int h = 0; h < 2; h++) {
            int row = bm + a_r + h * 64;
            float4 v = make_float4(0.f, 0.f, 0.f, 0.f);
            if (row < M) v = *(const float4*)(A + (size_t)row * K + k0 + a_k);
            As[a_k + 0][a_r + h * 64] = v.x;
            As[a_k + 1][a_r + h * 64] = v.y;
            As[a_k + 2][a_r + h * 64] = v.z;
            As[a_k + 3][a_r + h * 64] = v.w;
        }
        {
            float4 v = *(const float4*)(B + (size_t)(k0 + b_k) * Nn + bn + b_n);
            Bs[b_k][b_n + 0] = v.x;
            Bs[b_k][b_n + 1] = v.y;
            Bs[b_k][b_n + 2] = v.z;
            Bs[b_k][b_n + 3] = v.w;
        }
        __syncthreads();
#pragma unroll
        for (int kk = 0; kk < 16; kk++) {
            float ar[8], br[4];
#pragma unroll
            for (int i = 0; i < 8; i++) ar[i] = As[kk][ty * 8 + i];
#pragma unroll
            for (int j = 0; j < 4; j++) br[j] = Bs[kk][tx * 4 + j];
#pragma unroll
            for (int i = 0; i < 8; i++)
#pragma unroll
                for (int j = 0; j < 4; j++) acc[i][j] += ar[i] * br[j];
        }
        __syncthreads();
    }

    float a = act ? act[0] : 0.f;
#pragma unroll
    for (int i = 0; i < 8; i++) {
        int row = bm + ty * 8 + i;
        if (row >= M) continue;
        size_t base = (size_t)row * Nn + bn + tx * 4;
        float4 v;
        float* pv = &v.x;
#pragma unroll
        for (int j = 0; j < 4; j++) {
            float t = acc[i][j];
            if (Cadd) t += Cadd[base + j];
            if (act)  t = (t >= 0.f) ? t : a * t;
            pv[j] = t;
        }
        *(float4*)(Cout + base) = v;
    }
}

// --------------------------------- host ------------------------------------
static inline void* sym_addr(const void* sym) {
    void* p = nullptr;
    cudaGetSymbolAddress(&p, sym);
    return p;
}

extern "C" void kernel_launch(void* const* d_in, const int* in_sizes, int n_in,
                              void* d_out, int out_size) {
    const float* seq  = (const float*)d_in[0];
    const int*   ei   = (const int*)  d_in[1];
    const float* ew   = (const float*)d_in[2];
    const float* W1   = (const float*)d_in[3];
    const float* b1   = (const float*)d_in[4];
    const float* W2   = (const float*)d_in[5];
    const float* b2   = (const float*)d_in[6];
    const float* a1   = (const float*)d_in[7];
    const float* a2   = (const float*)d_in[8];
    const float* a3   = (const float*)d_in[9];
    const float* Wfc1 = (const float*)d_in[10];
    const float* Wfc2 = (const float*)d_in[11];
    const float* Wfc3 = (const float*)d_in[12];
    const float* Wfc4 = (const float*)d_in[13];

    const int* srcp = ei;
    const int* dstp = ei + N_EDGES;

    float* out_x = (float*)d_out;                       // [N, 128]
    float* out_f = out_x + (size_t)N_NODES * H_C;       // [N, 64]

    float* H1  = (float*)sym_addr(g_H1);
    float* X1  = (float*)sym_addr(g_X1);
    float* H2  = (float*)sym_addr(g_H2);
    float* T   = (float*)sym_addr(g_T);
    float* M34 = (float*)sym_addr(g_M34);
    float* U   = (float*)sym_addr(g_U);
    float* V   = (float*)sym_addr(g_V);
    int*   deg = (int*)  sym_addr(g_deg);

    const int ZB = (N_NODES + 255) / 256;   // 196
    const int EB = (N_EDGES + 255) / 256;   // 3125

    // -------- CSR build (by dst) --------
    k_zero_int<<<ZB, 256>>>(deg, N_NODES);
    k_count<<<EB, 256>>>(dstp);
    k_blocksum<<<NB_SCAN, 256>>>();
    k_scanpart<<<1, 256>>>();
    k_scanfinal<<<NB_SCAN, 256>>>();
    k_zero_int<<<ZB, 256>>>(deg, N_NODES);   // reuse as fill cursor
    k_fill<<<EB, 256>>>(srcp, dstp, ew);

    // -------- GCN layer 1: H1 = seq @ W1 ; X1 = prelu(agg(H1) + b1, a1) -----
    {
        dim3 grid(H2_C / 64, (N_NODES + 127) / 128);
        k_gemm<<<grid, 256>>>(seq, W1, nullptr, nullptr, H1, N_NODES, IN_C, H2_C);
    }
    k_agg<H2_C><<<(N_NODES + 7) / 8, 256>>>(H1, b1, a1, X1);

    // -------- GCN layer 2: H2 = X1 @ W2 ; x = prelu(agg(H2) + b2, a2) -------
    {
        dim3 grid(H_C / 64, (N_NODES + 127) / 128);
        k_gemm<<<grid, 256>>>(X1, W2, nullptr, nullptr, H2, N_NODES, H2_C, H_C);
    }
    k_agg<H_C><<<(N_NODES + 7) / 8, 256>>>(H2, b2, a2, out_x);

    // -------- combined epilogue weights (tiny GEMMs) ------------------------
    // M34 = Wfc3 @ Wfc4                [512,128]@[128,64]
    {
        dim3 grid(OUT_C / 64, (512 + 127) / 128);
        k_gemm<<<grid, 256>>>(Wfc3, Wfc4, nullptr, nullptr, M34, 512, 128, OUT_C);
    }
    // U = Wfc2 @ M34[:256]             [256,256]@[256,64]
    {
        dim3 grid(OUT_C / 64, (256 + 127) / 128);
        k_gemm<<<grid, 256>>>(Wfc2, M34, nullptr, nullptr, U, 256, 256, OUT_C);
    }
    // V = Wfc1 @ M34[256:]             [128,256]@[256,64]
    {
        dim3 grid(OUT_C / 64, 1);
        k_gemm<<<grid, 256>>>(Wfc1, M34 + 256 * OUT_C, nullptr, nullptr, V, 128, 256, OUT_C);
    }

    // -------- feat1 = prelu(seq @ U + x @ V, a3) ----------------------------
    {
        dim3 grid(OUT_C / 64, (N_NODES + 127) / 128);
        k_gemm<<<grid, 256>>>(seq, U, nullptr, nullptr, T, N_NODES, IN_C, OUT_C);
        k_gemm<<<grid, 256>>>(out_x, V, T, a3, out_f, N_NODES, H_C, OUT_C);
    }
}

// round 16
// speedup vs baseline: 1.3941x; 1.3941x over previous
#include <cuda_runtime.h>
#include <cuda_bf16.h>
#include <cstddef>
#include <cstdint>

// Problem constants (fixed by dataset)
#define N_NODES 50000
#define N_EDGES 800000
#define IN_C    256
#define H2_C    256   // 2*H
#define H_C     128
#define OUT_C   64

// ======================= scratch (device globals) ==========================
__device__ float g_H1 [(size_t)N_NODES * H2_C];
__device__ float g_X1 [(size_t)N_NODES * H2_C];
__device__ float g_H2 [(size_t)N_NODES * H_C];
__device__ float g_M34[512 * OUT_C];
__device__ float g_U  [256 * OUT_C];
__device__ float g_V  [128 * OUT_C];
__device__ int   g_deg[N_NODES];
__device__ int   g_rowptr[N_NODES + 1];
__device__ int   g_part[256];
__device__ int   g_csr_src[N_EDGES];
__device__ float g_csr_w [N_EDGES];
// pre-transposed/split weights (bf16 hi/lo), layout [N][K]
__device__ __nv_bfloat16 g_W1T_h[256 * 256], g_W1T_l[256 * 256];
__device__ __nv_bfloat16 g_W2T_h[128 * 256], g_W2T_l[128 * 256];
__device__ __nv_bfloat16 g_UVT_h[64 * 384],  g_UVT_l[64 * 384];

static const int NB_SCAN = (N_NODES + 255) / 256;

// ======================= CSR build =========================================
__global__ void k_zero_int(int* p, int n) {
    int i = blockIdx.x * blockDim.x + threadIdx.x;
    if (i < n) p[i] = 0;
}
__global__ void k_count(const int* __restrict__ dst) {
    int e = blockIdx.x * blockDim.x + threadIdx.x;
    if (e < N_EDGES) atomicAdd(&g_deg[dst[e]], 1);
}
__global__ void k_blocksum() {
    __shared__ int s[256];
    int t = threadIdx.x;
    int i = blockIdx.x * 256 + t;
    s[t] = (i < N_NODES) ? g_deg[i] : 0;
    __syncthreads();
    for (int off = 128; off > 0; off >>= 1) {
        if (t < off) s[t] += s[t + off];
        __syncthreads();
    }
    if (t == 0) g_part[blockIdx.x] = s[0];
}
__global__ void k_scanpart() {
    __shared__ int s[256];
    int t = threadIdx.x;
    s[t] = (t < NB_SCAN) ? g_part[t] : 0;
    __syncthreads();
    for (int off = 1; off < 256; off <<= 1) {
        int add = (t >= off) ? s[t - off] : 0;
        __syncthreads();
        s[t] += add;
        __syncthreads();
    }
    g_part[t] = (t == 0) ? 0 : s[t - 1];
}
__global__ void k_scanfinal() {
    __shared__ int s[256];
    int t = threadIdx.x;
    int i = blockIdx.x * 256 + t;
    int v = (i < N_NODES) ? g_deg[i] : 0;
    s[t] = v;
    __syncthreads();
    for (int off = 1; off < 256; off <<= 1) {
        int add = (t >= off) ? s[t - off] : 0;
        __syncthreads();
        s[t] += add;
        __syncthreads();
    }
    if (i < N_NODES) g_rowptr[i + 1] = s[t] + g_part[blockIdx.x];
    if (i == 0)      g_rowptr[0] = 0;
}
__global__ void k_fill(const int* __restrict__ src, const int* __restrict__ dst,
                       const float* __restrict__ w) {
    int e = blockIdx.x * blockDim.x + threadIdx.x;
    if (e >= N_EDGES) return;
    int d = dst[e];
    int pos = g_rowptr[d] + atomicAdd(&g_deg[d], 1);
    g_csr_src[pos] = src[e];
    g_csr_w [pos] = w[e];
}

// ================== CSR aggregation: one warp/node, fused bias+PReLU =======
template <int C>
__global__ void k_agg(const float* __restrict__ h,
                      const float* __restrict__ bias,
                      const float* __restrict__ act,
                      float* __restrict__ out) {
    int gw   = (blockIdx.x * blockDim.x + threadIdx.x) >> 5;
    int lane = threadIdx.x & 31;
    if (gw >= N_NODES) return;
    constexpr int V4 = C / 128;
    float4 acc[V4];
#pragma unroll
    for (int i = 0; i < V4; i++) acc[i] = make_float4(0.f, 0.f, 0.f, 0.f);
    int beg = g_rowptr[gw], end = g_rowptr[gw + 1];
    for (int j = beg; j < end; j++) {
        int   s = g_csr_src[j];
        float w = g_csr_w[j];
        const float4* row = (const float4*)(h + (size_t)s * C);
#pragma unroll
        for (int i = 0; i < V4; i++) {
            float4 v = row[lane + 32 * i];
            acc[i].x += w * v.x; acc[i].y += w * v.y;
            acc[i].z += w * v.z; acc[i].w += w * v.w;
        }
    }
    float a = act[0];
    const float4* b4 = (const float4*)bias;
    float4* o4 = (float4*)(out + (size_t)gw * C);
#pragma unroll
    for (int i = 0; i < V4; i++) {
        float4 bv = b4[lane + 32 * i];
        float4 r;
        r.x = acc[i].x + bv.x; r.x = r.x >= 0.f ? r.x : a * r.x;
        r.y = acc[i].y + bv.y; r.y = r.y >= 0.f ? r.y : a * r.y;
        r.z = acc[i].z + bv.z; r.z = r.z >= 0.f ? r.z : a * r.z;
        r.w = acc[i].w + bv.w; r.w = r.w >= 0.f ? r.w : a * r.w;
        o4[lane + 32 * i] = r;
    }
}

// ================== fp32 SGEMM (small weight GEMMs only) ===================
__global__ __launch_bounds__(256)
void k_gemm(const float* __restrict__ A, const float* __restrict__ B,
            float* __restrict__ Cout, int M, int K, int Nn) {
    __shared__ float As[16][128];
    __shared__ float Bs[16][64];
    const int tid = threadIdx.x;
    const int tx = tid & 15;
    const int ty = tid >> 4;
    const int bm = blockIdx.y * 128;
    const int bn = blockIdx.x * 64;
    const int a_r = tid >> 2;
    const int a_k = (tid & 3) << 2;
    const int b_k = tid >> 4;
    const int b_n = (tid & 15) << 2;
    float acc[8][4];
#pragma unroll
    for (int i = 0; i < 8; i++)
#pragma unroll
        for (int j = 0; j < 4; j++) acc[i][j] = 0.f;
    for (int k0 = 0; k0 < K; k0 += 16) {
#pragma unroll
        for (int h = 0; h < 2; h++) {
            int row = bm + a_r + h * 64;
            float4 v = make_float4(0.f, 0.f, 0.f, 0.f);
            if (row < M) v = *(const float4*)(A + (size_t)row * K + k0 + a_k);
            As[a_k + 0][a_r + h * 64] = v.x;
            As[a_k + 1][a_r + h * 64] = v.y;
            As[a_k + 2][a_r + h * 64] = v.z;
            As[a_k + 3][a_r + h * 64] = v.w;
        }
        {
            float4 v = *(const float4*)(B + (size_t)(k0 + b_k) * Nn + bn + b_n);
            Bs[b_k][b_n + 0] = v.x; Bs[b_k][b_n + 1] = v.y;
            Bs[b_k][b_n + 2] = v.z; Bs[b_k][b_n + 3] = v.w;
        }
        __syncthreads();
#pragma unroll
        for (int kk = 0; kk < 16; kk++) {
            float ar[8], br[4];
#pragma unroll
            for (int i = 0; i < 8; i++) ar[i] = As[kk][ty * 8 + i];
#pragma unroll
            for (int j = 0; j < 4; j++) br[j] = Bs[kk][tx * 4 + j];
#pragma unroll
            for (int i = 0; i < 8; i++)
#pragma unroll
                for (int j = 0; j < 4; j++) acc[i][j] += ar[i] * br[j];
        }
        __syncthreads();
    }
#pragma unroll
    for (int i = 0; i < 8; i++) {
        int row = bm + ty * 8 + i;
        if (row >= M) continue;
        size_t base = (size_t)row * Nn + bn + tx * 4;
        float4 v = make_float4(acc[i][0], acc[i][1], acc[i][2], acc[i][3]);
        *(float4*)(Cout + base) = v;
    }
}

// ============== weight transpose + hi/lo bf16 split (tiny) =================
__global__ void k_convT(const float* __restrict__ in, int K, int N,
                        __nv_bfloat16* __restrict__ oh, __nv_bfloat16* __restrict__ ol,
                        int ldo, int koff) {
    int idx = blockIdx.x * blockDim.x + threadIdx.x;
    if (idx >= K * N) return;
    int k = idx / N, n = idx % N;
    float x = in[idx];
    __nv_bfloat16 h = __float2bfloat16_rn(x);
    float r = x - __bfloat162float(h);
    __nv_bfloat16 l = __float2bfloat16_rn(r);
    oh[(size_t)n * ldo + koff + k] = h;
    ol[(size_t)n * ldo + koff + k] = l;
}

// ============== HMMA (mma.sync) split-bf16 GEMM ============================
// C[M x NT] = A[M x KTOT] @ Bt^T, Bt stored [NT][KTOT] bf16 hi/lo (row-major).
// A fp32, split hi/lo in the loader. A = concat(A1[:, :K1], A2[:, :KTOT-K1]).
// Optional fused PReLU via act pointer.

#define LDSM_X4(r, addr) \
    asm volatile("ldmatrix.sync.aligned.m8n8.x4.shared.b16 {%0,%1,%2,%3}, [%4];" \
        : "=r"((r)[0]), "=r"((r)[1]), "=r"((r)[2]), "=r"((r)[3]) : "r"(addr))

#define MMA16816(d, a, b0, b1) \
    asm volatile("mma.sync.aligned.m16n8k16.row.col.f32.bf16.bf16.f32 " \
        "{%0,%1,%2,%3}, {%4,%5,%6,%7}, {%8,%9}, {%0,%1,%2,%3};" \
        : "+f"((d)[0]), "+f"((d)[1]), "+f"((d)[2]), "+f"((d)[3]) \
        : "r"((a)[0]), "r"((a)[1]), "r"((a)[2]), "r"((a)[3]), "r"(b0), "r"(b1))

__device__ __forceinline__ uint32_t smem_u32(const void* p) {
    uint32_t a;
    asm("{ .reg .u64 t; cvta.to.shared.u64 t, %1; cvt.u32.u64 %0, t; }"
        : "=r"(a) : "l"(p));
    return a;
}

// Split 2 floats into packed hi/lo bf16x2
__device__ __forceinline__ void split2(float x, float y, uint32_t& h, uint32_t& l) {
    __nv_bfloat162 hh = __floats2bfloat162_rn(x, y);
    float rx = x - __bfloat162float(hh.x);
    float ry = y - __bfloat162float(hh.y);
    __nv_bfloat162 ll = __floats2bfloat162_rn(rx, ry);
    h = *(uint32_t*)&hh;
    l = *(uint32_t*)&ll;
}

// smem layout per stage (bytes): A_hi[128][40h]=10240, A_lo=10240,
// B_hi[64][40h]=5120, B_lo=5120  => 30720/stage, 2 stages = 61440.
#define ST_SZ   30720
#define OFF_AH  0
#define OFF_AL  10240
#define OFF_BH  20480
#define OFF_BL  25600
#define ROWB    80        // smem row stride in bytes (40 halves)

template <int NT, int KTOT>
__global__ __launch_bounds__(256, 2)
void hm_gemm(const float* __restrict__ A1, int lda1, int K1,
             const float* __restrict__ A2, int lda2,
             const __nv_bfloat16* __restrict__ Bth,
             const __nv_bfloat16* __restrict__ Btl,
             const float* __restrict__ act,
             float* __restrict__ C, int M) {
    extern __shared__ char smem[];
    const uint32_t sb = smem_u32(smem);
    const int tid  = threadIdx.x;
    const int wid  = tid >> 5;
    const int lane = tid & 31;
    const int wm = wid & 3;          // 0..3  (m offset wm*32)
    const int wn = wid >> 2;         // 0..1  (n offset wn*32)
    const int bm = blockIdx.x * 128;
    const int bn = blockIdx.y * 64;  // global col / Bt row offset

    constexpr int NC = KTOT / 32;

    // global-load indices
    const int arow = tid >> 1;            // 0..127
    const int acol = (tid & 1) * 16;      // 0 or 16 (floats)
    const int brow = tid >> 2;            // 0..63
    const int bseg = tid & 3;             // 16B segment

    float acc[2][4][4];
#pragma unroll
    for (int i = 0; i < 2; i++)
#pragma unroll
        for (int j = 0; j < 4; j++)
#pragma unroll
            for (int q = 0; q < 4; q++) acc[i][j][q] = 0.f;

    float4 avr[4];
    uint4  bhr, blr;

    // ---- helpers as lambdas ----
    auto load_global = [&](int c) {
        const int k0 = c * 32;
        const float* Ap; int lda, kk;
        if (k0 < K1) { Ap = A1; lda = lda1; kk = k0; }
        else         { Ap = A2; lda = lda2; kk = k0 - K1; }
        int grow = bm + arow;
        if (grow < M) {
            const float4* p = (const float4*)(Ap + (size_t)grow * lda + kk + acol);
#pragma unroll
            for (int i = 0; i < 4; i++) avr[i] = p[i];
        } else {
#pragma unroll
            for (int i = 0; i < 4; i++) avr[i] = make_float4(0.f, 0.f, 0.f, 0.f);
        }
        const __nv_bfloat16* bh = Bth + (size_t)(bn + brow) * KTOT + k0 + bseg * 8;
        const __nv_bfloat16* bl = Btl + (size_t)(bn + brow) * KTOT + k0 + bseg * 8;
        bhr = *(const uint4*)bh;
        blr = *(const uint4*)bl;
    };

    auto store_smem = [&](int stage) {
        uint32_t h[8], l[8];
#pragma unroll
        for (int i = 0; i < 4; i++) {
            split2(avr[i].x, avr[i].y, h[2 * i],     l[2 * i]);
            split2(avr[i].z, avr[i].w, h[2 * i + 1], l[2 * i + 1]);
        }
        uint32_t aoff = arow * ROWB + acol * 2;   // bytes
        *(uint4*)(smem + (size_t)stage * ST_SZ + OFF_AH + aoff)      = make_uint4(h[0], h[1], h[2], h[3]);
        *(uint4*)(smem + (size_t)stage * ST_SZ + OFF_AH + aoff + 16) = make_uint4(h[4], h[5], h[6], h[7]);
        *(uint4*)(smem + (size_t)stage * ST_SZ + OFF_AL + aoff)      = make_uint4(l[0], l[1], l[2], l[3]);
        *(uint4*)(smem + (size_t)stage * ST_SZ + OFF_AL + aoff + 16) = make_uint4(l[4], l[5], l[6], l[7]);
        uint32_t boff = brow * ROWB + bseg * 16;
        *(uint4*)(smem + (size_t)stage * ST_SZ + OFF_BH + boff) = bhr;
        *(uint4*)(smem + (size_t)stage * ST_SZ + OFF_BL + boff) = blr;
    };

    auto compute = [&](int stage) {
        uint32_t sA_h = sb + stage * ST_SZ + OFF_AH;
        uint32_t sA_l = sb + stage * ST_SZ + OFF_AL;
        uint32_t sB_h = sb + stage * ST_SZ + OFF_BH;
        uint32_t sB_l = sb + stage * ST_SZ + OFF_BL;
        const int lrow  = lane & 15;
        const int lcol8 = lane >> 4;
#pragma unroll
        for (int kk = 0; kk < 32; kk += 16) {
            uint32_t Ah[2][4], Al[2][4], Bh[2][4], Bl[2][4];
#pragma unroll
            for (int mt = 0; mt < 2; mt++) {
                uint32_t aoff = (uint32_t)(wm * 32 + mt * 16 + lrow) * ROWB
                              + (kk + lcol8 * 8) * 2;
                LDSM_X4(Ah[mt], sA_h + aoff);
                LDSM_X4(Al[mt], sA_l + aoff);
            }
#pragma unroll
            for (int p = 0; p < 2; p++) {
                uint32_t boff = (uint32_t)(wn * 32 + p * 16 + lrow) * ROWB
                              + (kk + lcol8 * 8) * 2;
                LDSM_X4(Bh[p], sB_h + boff);
                LDSM_X4(Bl[p], sB_l + boff);
            }
#pragma unroll
            for (int mt = 0; mt < 2; mt++) {
#pragma unroll
                for (int nt = 0; nt < 4; nt++) {
                    int p = nt >> 1, o = nt & 1;
                    MMA16816(acc[mt][nt], Ah[mt], Bh[p][o], Bh[p][o + 2]);
                    MMA16816(acc[mt][nt], Ah[mt], Bl[p][o], Bl[p][o + 2]);
                    MMA16816(acc[mt][nt], Al[mt], Bh[p][o], Bh[p][o + 2]);
                }
            }
        }
    };

    // ---- pipeline ----
    load_global(0);
    store_smem(0);
    __syncthreads();
    for (int c = 0; c < NC; c++) {
        int stage = c & 1;
        if (c + 1 < NC) load_global(c + 1);
        compute(stage);
        if (c + 1 < NC) store_smem(stage ^ 1);
        __syncthreads();
    }

    // ---- epilogue ----
    const bool hasAct = (act != nullptr);
    const float av = hasAct ? act[0] : 0.f;
    const int g = lane >> 2, t = lane & 3;
#pragma unroll
    for (int mt = 0; mt < 2; mt++) {
#pragma unroll
        for (int nt = 0; nt < 4; nt++) {
            int row0 = bm + wm * 32 + mt * 16 + g;
            int col  = bn + wn * 32 + nt * 8 + 2 * t;
            float c0 = acc[mt][nt][0], c1 = acc[mt][nt][1];
            float c2 = acc[mt][nt][2], c3 = acc[mt][nt][3];
            if (hasAct) {
                c0 = c0 >= 0.f ? c0 : av * c0;
                c1 = c1 >= 0.f ? c1 : av * c1;
                c2 = c2 >= 0.f ? c2 : av * c2;
                c3 = c3 >= 0.f ? c3 : av * c3;
            }
            if (row0 < M)     *(float2*)(C + (size_t)row0 * NT + col)       = make_float2(c0, c1);
            if (row0 + 8 < M) *(float2*)(C + (size_t)(row0 + 8) * NT + col) = make_float2(c2, c3);
        }
    }
}

// --------------------------------- host ------------------------------------
static inline void* sym_addr(const void* sym) {
    void* p = nullptr;
    cudaGetSymbolAddress(&p, sym);
    return p;
}

extern "C" void kernel_launch(void* const* d_in, const int* in_sizes, int n_in,
                              void* d_out, int out_size) {
    const float* seq  = (const float*)d_in[0];
    const int*   ei   = (const int*)  d_in[1];
    const float* ew   = (const float*)d_in[2];
    const float* W1   = (const float*)d_in[3];
    const float* b1   = (const float*)d_in[4];
    const float* W2   = (const float*)d_in[5];
    const float* b2   = (const float*)d_in[6];
    const float* a1   = (const float*)d_in[7];
    const float* a2   = (const float*)d_in[8];
    const float* a3   = (const float*)d_in[9];
    const float* Wfc1 = (const float*)d_in[10];
    const float* Wfc2 = (const float*)d_in[11];
    const float* Wfc3 = (const float*)d_in[12];
    const float* Wfc4 = (const float*)d_in[13];

    const int* srcp = ei;
    const int* dstp = ei + N_EDGES;

    float* out_x = (float*)d_out;                   // [N, 128]
    float* out_f = out_x + (size_t)N_NODES * H_C;   // [N, 64]

    float* H1  = (float*)sym_addr(g_H1);
    float* X1  = (float*)sym_addr(g_X1);
    float* H2  = (float*)sym_addr(g_H2);
    float* M34 = (float*)sym_addr(g_M34);
    float* U   = (float*)sym_addr(g_U);
    float* V   = (float*)sym_addr(g_V);
    int*   deg = (int*)  sym_addr(g_deg);
    __nv_bfloat16* W1Th = (__nv_bfloat16*)sym_addr(g_W1T_h);
    __nv_bfloat16* W1Tl = (__nv_bfloat16*)sym_addr(g_W1T_l);
    __nv_bfloat16* W2Th = (__nv_bfloat16*)sym_addr(g_W2T_h);
    __nv_bfloat16* W2Tl = (__nv_bfloat16*)sym_addr(g_W2T_l);
    __nv_bfloat16* UVTh = (__nv_bfloat16*)sym_addr(g_UVT_h);
    __nv_bfloat16* UVTl = (__nv_bfloat16*)sym_addr(g_UVT_l);

    const int ZB = (N_NODES + 255) / 256;
    const int EB = (N_EDGES + 255) / 256;
    const int MT = (N_NODES + 127) / 128;   // 391

    cudaFuncSetAttribute(hm_gemm<256, 256>, cudaFuncAttributeMaxDynamicSharedMemorySize, 2 * ST_SZ);
    cudaFuncSetAttribute(hm_gemm<128, 256>, cudaFuncAttributeMaxDynamicSharedMemorySize, 2 * ST_SZ);
    cudaFuncSetAttribute(hm_gemm<64, 384>,  cudaFuncAttributeMaxDynamicSharedMemorySize, 2 * ST_SZ);

    // -------- CSR build (by dst) --------
    k_zero_int<<<ZB, 256>>>(deg, N_NODES);
    k_count<<<EB, 256>>>(dstp);
    k_blocksum<<<NB_SCAN, 256>>>();
    k_scanpart<<<1, 256>>>();
    k_scanfinal<<<NB_SCAN, 256>>>();
    k_zero_int<<<ZB, 256>>>(deg, N_NODES);
    k_fill<<<EB, 256>>>(srcp, dstp, ew);

    // -------- weight transpose/split --------
    k_convT<<<(256 * 256 + 255) / 256, 256>>>(W1, 256, 256, W1Th, W1Tl, 256, 0);
    k_convT<<<(256 * 128 + 255) / 256, 256>>>(W2, 256, 128, W2Th, W2Tl, 256, 0);

    // -------- GCN layer 1: H1 = seq @ W1 (HMMA), X1 = prelu(agg+b1) --------
    {
        dim3 grid(MT, H2_C / 64);
        hm_gemm<256, 256><<<grid, 256, 2 * ST_SZ>>>(
            seq, 256, 256, nullptr, 0, W1Th, W1Tl, nullptr, H1, N_NODES);
    }
    k_agg<H2_C><<<(N_NODES + 7) / 8, 256>>>(H1, b1, a1, X1);

    // -------- GCN layer 2: H2 = X1 @ W2 (HMMA), x = prelu(agg+b2) ----------
    {
        dim3 grid(MT, H_C / 64);
        hm_gemm<128, 256><<<grid, 256, 2 * ST_SZ>>>(
            X1, 256, 256, nullptr, 0, W2Th, W2Tl, nullptr, H2, N_NODES);
    }
    k_agg<H_C><<<(N_NODES + 7) / 8, 256>>>(H2, b2, a2, out_x);

    // -------- combined epilogue weights (tiny fp32 GEMMs) ------------------
    {
        dim3 grid(1, 4);
        k_gemm<<<grid, 256>>>(Wfc3, Wfc4, M34, 512, 128, OUT_C);
    }
    {
        dim3 grid(1, 2);
        k_gemm<<<grid, 256>>>(Wfc2, M34, U, 256, 256, OUT_C);
    }
    {
        dim3 grid(1, 1);
        k_gemm<<<grid, 256>>>(Wfc1, M34 + 256 * OUT_C, V, 128, 256, OUT_C);
    }
    // UVT = [U;V]^T as [64][384] hi/lo
    k_convT<<<(256 * 64 + 255) / 256, 256>>>(U, 256, 64, UVTh, UVTl, 384, 0);
    k_convT<<<(128 * 64 + 255) / 256, 256>>>(V, 128, 64, UVTh, UVTl, 384, 256);

    // -------- feat1 = prelu([seq | x] @ [U;V], a3) -------------------------
    {
        dim3 grid(MT, 1);
        hm_gemm<64, 384><<<grid, 256, 2 * ST_SZ>>>(
            seq, 256, 256, out_x, 128, UVTh, UVTl, a3, out_f, N_NODES);
    }
}